// round 9
// baseline (speedup 1.0000x reference)
#include <cuda_runtime.h>
#include <cuda_bf16.h>
#include <stdint.h>
#include <math.h>

#define NMAX 50000
#define EPS_LN 1e-5f
#define EPW 16

typedef unsigned long long u64;

// ---------------- scratch ----------------
// g_PQ: P (= x@W_top + sp_b1) cols 0-255, Q (= x@W_bot) cols 256-511
__device__ float g_PQ[(size_t)NMAX * 512];
__device__ float g_Hfr[(size_t)NMAX * 128];   // x @ fr_w1 (bias added in role)
__device__ float g_Hph[(size_t)NMAX * 256];   // x @ ph_w1 (bias added in role)
__device__ __align__(16) __nv_bfloat16 g_Bhi[896 * 64];  // [n][k] transposed weights
__device__ __align__(16) __nv_bfloat16 g_Blo[896 * 64];

// ---------------- f32x2 packed helpers ----------------
__device__ __forceinline__ u64 f2pack(float lo, float hi) {
    u64 r; asm("mov.b64 %0, {%1, %2};" : "=l"(r) : "f"(lo), "f"(hi)); return r;
}
__device__ __forceinline__ void f2unpack(u64 v, float& lo, float& hi) {
    asm("mov.b64 {%0, %1}, %2;" : "=f"(lo), "=f"(hi) : "l"(v));
}
__device__ __forceinline__ u64 dup2(float v) { return f2pack(v, v); }
__device__ __forceinline__ u64 fma2(u64 a, u64 b, u64 c) {
    u64 d; asm("fma.rn.f32x2 %0, %1, %2, %3;" : "=l"(d) : "l"(a), "l"(b), "l"(c)); return d;
}
__device__ __forceinline__ u64 add2(u64 a, u64 b) {
    u64 d; asm("add.rn.f32x2 %0, %1, %2;" : "=l"(d) : "l"(a), "l"(b)); return d;
}
__device__ __forceinline__ u64 mul2(u64 a, u64 b) {
    u64 d; asm("mul.rn.f32x2 %0, %1, %2;" : "=l"(d) : "l"(a), "l"(b)); return d;
}
__device__ __forceinline__ float rcp_fast(float x) {
    float r; asm("rcp.approx.f32 %0, %1;" : "=f"(r) : "f"(x)); return r;
}
__device__ __forceinline__ float ex2_fast(float x) {
    float r; asm("ex2.approx.f32 %0, %1;" : "=f"(r) : "f"(x)); return r;
}

__device__ __forceinline__ float wredsum(float v) {
#pragma unroll
    for (int o = 16; o > 0; o >>= 1) v += __shfl_xor_sync(0xffffffffu, v, o);
    return v;
}
__device__ __forceinline__ void wredsum2(float& a, float& b) {
#pragma unroll
    for (int o = 16; o > 0; o >>= 1) {
        float ta = __shfl_xor_sync(0xffffffffu, a, o);
        float tb = __shfl_xor_sync(0xffffffffu, b, o);
        a += ta;
        b += tb;
    }
}

// fast GELU via Hastings 3-term erf (A&S 7.1.25, |err| <= 2.5e-5)
__device__ __forceinline__ float gelu_fast(float u) {
    float z = 0.70710678118654752f * u;
    float az = fabsf(z);
    float t = rcp_fast(fmaf(0.47047f, az, 1.0f));
    float poly = t * fmaf(t, fmaf(t, 0.7478556f, -0.0958798f), 0.3480242f);
    float e = ex2_fast(-az * az * 1.4426950408889634f);
    float erf_z = copysignf(fmaf(-poly, e, 1.0f), z);
    return 0.5f * u * (1.0f + erf_z);
}

// ---------------- mma.sync bf16 (portable HMMA, no 'a'-features) ----------------
__device__ __forceinline__ void mma_bf16(float* d, const uint32_t* a, uint32_t b0, uint32_t b1) {
    asm volatile(
        "mma.sync.aligned.m16n8k16.row.col.f32.bf16.bf16.f32 "
        "{%0,%1,%2,%3}, {%4,%5,%6,%7}, {%8,%9}, {%0,%1,%2,%3};"
        : "+f"(d[0]), "+f"(d[1]), "+f"(d[2]), "+f"(d[3])
        : "r"(a[0]), "r"(a[1]), "r"(a[2]), "r"(a[3]), "r"(b0), "r"(b1));
}

// pack float2 -> bf16x2 hi + residual lo
__device__ __forceinline__ void bf16_split2(float2 v, uint32_t& hi, uint32_t& lo) {
    __nv_bfloat16 h0 = __float2bfloat16(v.x);
    __nv_bfloat16 h1 = __float2bfloat16(v.y);
    __nv_bfloat16 l0 = __float2bfloat16(v.x - __bfloat162float(h0));
    __nv_bfloat16 l1 = __float2bfloat16(v.y - __bfloat162float(h1));
    __nv_bfloat162 hh = __halves2bfloat162(h0, h1);
    __nv_bfloat162 ll = __halves2bfloat162(l0, l1);
    hi = *reinterpret_cast<uint32_t*>(&hh);
    lo = *reinterpret_cast<uint32_t*>(&ll);
}

// ============================================================================
// prep: transpose + bf16-split the fused weight matrix [64, 896] -> [896][64]
// ============================================================================
__global__ void k_prep(const float* __restrict__ sp_w1, const float* __restrict__ fr_w1,
                       const float* __restrict__ ph_w1) {
    int idx = blockIdx.x * 256 + threadIdx.x;
    if (idx >= 896 * 64) return;
    int n = idx >> 6, k = idx & 63;
    float v;
    if (n < 256) v = sp_w1[k * 256 + n];
    else if (n < 512) v = sp_w1[(64 + k) * 256 + (n - 256)];
    else if (n < 640) v = fr_w1[k * 128 + (n - 512)];
    else v = ph_w1[k * 256 + (n - 640)];
    __nv_bfloat16 hi = __float2bfloat16(v);
    __nv_bfloat16 lo = __float2bfloat16(v - __bfloat162float(hi));
    g_Bhi[idx] = hi;
    g_Blo[idx] = lo;
}

// ============================================================================
// k_gemm1: x[N,64] @ Wcat[64,896] -> g_PQ (+sp_b1 on P) | g_Hfr | g_Hph
// bf16-split 3-term mma.sync (hi*hi + hi*lo + lo*hi). 64 nodes/block, 4 warps.
// No smem; A fragments register-resident, B from L1/L2-hot transposed weights.
// ============================================================================
__global__ __launch_bounds__(128) void k_gemm1(const float* __restrict__ x,
                                               const float* __restrict__ sp_b1, int N) {
    const int wid = threadIdx.x >> 5, lane = threadIdx.x & 31;
    const int g = lane >> 2, tig = lane & 3;
    const int m0 = blockIdx.x * 64 + wid * 16;
    const int r0 = m0 + g, r1 = m0 + g + 8;
    const bool v0 = r0 < N, v1 = r1 < N;

    // A fragments: [kstep][reg] hi/lo. reg order: {A[g][k0:1], A[g+8][k0:1], A[g][k8:9], A[g+8][k8:9]}
    uint32_t aHi[4][4], aLo[4][4];
#pragma unroll
    for (int ks = 0; ks < 4; ks++) {
        const float2 Z = make_float2(0.f, 0.f);
        float2 p00 = v0 ? *reinterpret_cast<const float2*>(x + (size_t)r0 * 64 + ks * 16 + tig * 2) : Z;
        float2 p01 = v0 ? *reinterpret_cast<const float2*>(x + (size_t)r0 * 64 + ks * 16 + tig * 2 + 8) : Z;
        float2 p10 = v1 ? *reinterpret_cast<const float2*>(x + (size_t)r1 * 64 + ks * 16 + tig * 2) : Z;
        float2 p11 = v1 ? *reinterpret_cast<const float2*>(x + (size_t)r1 * 64 + ks * 16 + tig * 2 + 8) : Z;
        bf16_split2(p00, aHi[ks][0], aLo[ks][0]);
        bf16_split2(p10, aHi[ks][1], aLo[ks][1]);
        bf16_split2(p01, aHi[ks][2], aLo[ks][2]);
        bf16_split2(p11, aHi[ks][3], aLo[ks][3]);
    }

    // N loop: 112 chunks of 8 columns
    const __nv_bfloat16* bh_base = g_Bhi + (size_t)g * 64;
    const __nv_bfloat16* bl_base = g_Blo + (size_t)g * 64;
#pragma unroll 2
    for (int nc = 0; nc < 112; nc++) {
        const __nv_bfloat16* bh = bh_base + (size_t)nc * 8 * 64;
        const __nv_bfloat16* bl = bl_base + (size_t)nc * 8 * 64;
        float acc[4] = {0.f, 0.f, 0.f, 0.f};
#pragma unroll
        for (int ks = 0; ks < 4; ks++) {
            uint32_t b0h = *reinterpret_cast<const uint32_t*>(bh + ks * 16 + tig * 2);
            uint32_t b1h = *reinterpret_cast<const uint32_t*>(bh + ks * 16 + tig * 2 + 8);
            uint32_t b0l = *reinterpret_cast<const uint32_t*>(bl + ks * 16 + tig * 2);
            uint32_t b1l = *reinterpret_cast<const uint32_t*>(bl + ks * 16 + tig * 2 + 8);
            mma_bf16(acc, aHi[ks], b0h, b1h);   // hi*hi
            mma_bf16(acc, aHi[ks], b0l, b1l);   // hi*lo
            mma_bf16(acc, aLo[ks], b0h, b1h);   // lo*hi
        }

        const int Cb = nc * 8;           // base output column of this chunk
        const int col = Cb + tig * 2;
        float2 o0 = make_float2(acc[0], acc[1]);
        float2 o1 = make_float2(acc[2], acc[3]);
        if (Cb < 256) {  // P region: fold sp_b1
            float2 bb = *reinterpret_cast<const float2*>(sp_b1 + col);
            o0.x += bb.x; o0.y += bb.y;
            o1.x += bb.x; o1.y += bb.y;
        }
        float* d0;
        float* d1;
        if (Cb < 512) {
            d0 = g_PQ + (size_t)r0 * 512 + col;
            d1 = g_PQ + (size_t)r1 * 512 + col;
        } else if (Cb < 640) {
            d0 = g_Hfr + (size_t)r0 * 128 + (col - 512);
            d1 = g_Hfr + (size_t)r1 * 128 + (col - 512);
        } else {
            d0 = g_Hph + (size_t)r0 * 256 + (col - 640);
            d1 = g_Hph + (size_t)r1 * 256 + (col - 640);
        }
        if (v0) *reinterpret_cast<float2*>(d0) = o0;
        if (v1) *reinterpret_cast<float2*>(d1) = o1;
    }
}

// ============================================================================
// Edge role: out = GELU(LN(P[row]+Q[col])) . w2 + b2   (P has sp_b1 folded)
// ============================================================================
__device__ __forceinline__ void edge_role(int eb, const int* __restrict__ ei, int E,
                                          const float* __restrict__ gm,
                                          const float* __restrict__ bt,
                                          const float* __restrict__ w2,
                                          const float* __restrict__ b2p,
                                          float* __restrict__ out) {
    const int t = threadIdx.x;
    const int lane = t & 31;
    const int wid = t >> 5;

    long e0 = ((long)eb * 4 + wid) * EPW;
    if (e0 >= E) return;
    const int nE = (int)(E - e0 < EPW ? E - e0 : EPW);

    const float4* gmv = reinterpret_cast<const float4*>(gm);
    const float4* btv = reinterpret_cast<const float4*>(bt);
    const float4* w2v = reinterpret_cast<const float4*>(w2);
    float4 rga = gmv[lane], rgb = gmv[32 + lane];
    float4 rba = btv[lane], rbb = btv[32 + lane];
    float4 rwa = w2v[lane], rwb = w2v[32 + lane];

    const float RS2 = 0.70710678118654752f;
    u64 g2[4] = {f2pack(rga.x * RS2, rga.y * RS2), f2pack(rga.z * RS2, rga.w * RS2),
                 f2pack(rgb.x * RS2, rgb.y * RS2), f2pack(rgb.z * RS2, rgb.w * RS2)};
    u64 be2[4] = {f2pack(rba.x * RS2, rba.y * RS2), f2pack(rba.z * RS2, rba.w * RS2),
                  f2pack(rbb.x * RS2, rbb.y * RS2), f2pack(rbb.z * RS2, rbb.w * RS2)};
    u64 hw2[4] = {f2pack(rwa.x * RS2, rwa.y * RS2), f2pack(rwa.z * RS2, rwa.w * RS2),
                  f2pack(rwb.x * RS2, rwb.y * RS2), f2pack(rwb.z * RS2, rwb.w * RS2)};

    const u64 ONE2 = dup2(1.0f);
    const u64 PC = dup2(0.47047f);
    const u64 C3 = dup2(-0.7478556f);
    const u64 C2C = dup2(0.0958798f);
    const u64 C1 = dup2(-0.3480242f);
    const u64 NL2E = dup2(-1.4426950408889634f);
    const u64 AMASK = 0x7FFFFFFF7FFFFFFFull;
    const u64 SMASK = 0x8000000080000000ull;

    const float b2 = __ldg(b2p);

    const ulonglong2* PQ2 = reinterpret_cast<const ulonglong2*>(g_PQ);

    const int li = lane & 15;
    int idx = 0;
    if (li < nE) idx = ei[(lane < 16 ? e0 + li : (long)E + e0 + li)];

    int r = __shfl_sync(0xffffffffu, idx, 0);
    int c = __shfl_sync(0xffffffffu, idx, 16);
    ulonglong2 pa = PQ2[(size_t)r * 128 + lane];
    ulonglong2 pb = PQ2[(size_t)r * 128 + 32 + lane];
    ulonglong2 qa = PQ2[(size_t)c * 128 + 64 + lane];
    ulonglong2 qb = PQ2[(size_t)c * 128 + 96 + lane];

    for (int i = 0; i < nE; i++) {
        ulonglong2 pan = pa, pbn = pb, qan = qa, qbn = qb;
        if (i + 1 < nE) {
            int rn = __shfl_sync(0xffffffffu, idx, i + 1);
            int cn = __shfl_sync(0xffffffffu, idx, 17 + i);
            pan = PQ2[(size_t)rn * 128 + lane];
            pbn = PQ2[(size_t)rn * 128 + 32 + lane];
            qan = PQ2[(size_t)cn * 128 + 64 + lane];
            qbn = PQ2[(size_t)cn * 128 + 96 + lane];
        }

        u64 s0 = add2(pa.x, qa.x), s1 = add2(pa.y, qa.y);
        u64 s2 = add2(pb.x, qb.x), s3 = add2(pb.y, qb.y);

        u64 sum2 = add2(add2(s0, s1), add2(s2, s3));
        u64 sq2 = fma2(s0, s0, fma2(s1, s1, fma2(s2, s2, mul2(s3, s3))));
        float slo, shi, sqlo, sqhi;
        f2unpack(sum2, slo, shi);
        f2unpack(sq2, sqlo, sqhi);
        float sum = slo + shi;
        float sq = sqlo + sqhi;
        wredsum2(sum, sq);
        float mean = sum * (1.f / 256.f);
        float var = sq * (1.f / 256.f) - mean * mean;
        float rstd = rsqrtf(var + EPS_LN);
        u64 A2 = dup2(rstd);
        u64 Cc = dup2(-mean * rstd);

        u64 sarr[4] = {s0, s1, s2, s3};
        u64 acc2 = 0;
#pragma unroll
        for (int p = 0; p < 4; p++) {
            u64 un2 = fma2(sarr[p], A2, Cc);
            u64 z2 = fma2(un2, g2[p], be2[p]);
            u64 az2 = z2 & AMASK;
            u64 d2 = fma2(az2, PC, ONE2);
            float dl, dh;
            f2unpack(d2, dl, dh);
            u64 t2 = f2pack(rcp_fast(dl), rcp_fast(dh));
            u64 p2 = fma2(t2, C3, C2C);
            p2 = fma2(t2, p2, C1);
            p2 = mul2(p2, t2);
            u64 zz2 = mul2(az2, az2);
            u64 m2 = mul2(zz2, NL2E);
            float ml, mh;
            f2unpack(m2, ml, mh);
            u64 e2 = f2pack(ex2_fast(ml), ex2_fast(mh));
            u64 erf2 = fma2(p2, e2, ONE2);
            erf2 = erf2 | (z2 & SMASK);
            u64 op2 = add2(erf2, ONE2);
            u64 term2 = mul2(z2, op2);
            acc2 = fma2(term2, hw2[p], acc2);
        }
        float al, ah;
        f2unpack(acc2, al, ah);
        float acc = wredsum(al + ah);
        if (lane == 0) out[e0 + i] = acc + b2;

        pa = pan; pb = pbn; qa = qan; qb = qbn;
    }
}

// ============================================================================
// fr role: H_fr[16x128] + b1 -> LN -> GELU -> Linear(64). Two 64-thr subgroups.
// ============================================================================
__device__ __forceinline__ void fr_role(int nb, char* smem_raw,
                                        const float* __restrict__ b1,
                                        const float* __restrict__ gm,
                                        const float* __restrict__ bt,
                                        const float* __restrict__ w2,
                                        const float* __restrict__ b2,
                                        float* __restrict__ out, int N) {
    const int t = threadIdx.x;
    const int g = t >> 6;
    const int t64 = t & 63;
    float (*hs)[128] = reinterpret_cast<float (*)[128]>(smem_raw + g * 8192);
    const int n0 = nb * 32 + g * 16;

    {
        int rem = N - n0;
        int lim = (rem > 16 ? 16 : (rem < 0 ? 0 : rem)) * 32;  // in float4 units
        const float4* src4 = reinterpret_cast<const float4*>(g_Hfr + (size_t)n0 * 128);
        float4* hs4 = reinterpret_cast<float4*>(&hs[0][0]);
        float4 bv = reinterpret_cast<const float4*>(b1)[t64 & 31];
#pragma unroll
        for (int j = 0; j < 8; j++) {
            int idx = t64 + 64 * j;
            float4 v = make_float4(0.f, 0.f, 0.f, 0.f);
            if (idx < lim) v = __ldg(src4 + idx);
            v.x += bv.x; v.y += bv.y; v.z += bv.z; v.w += bv.w;
            hs4[idx] = v;
        }
    }
    __syncthreads();

    {
        const int w2i = t64 >> 5, lane = t & 31;
        float rg[4], rb[4];
#pragma unroll
        for (int q = 0; q < 4; q++) { rg[q] = gm[lane + 32 * q]; rb[q] = bt[lane + 32 * q]; }
        for (int mm = 0; mm < 8; mm++) {
            int m = w2i * 8 + mm;
            float v[4];
            float sum = 0.f, sq = 0.f;
#pragma unroll
            for (int q = 0; q < 4; q++) {
                v[q] = hs[m][lane + 32 * q];
                sum += v[q];
                sq = fmaf(v[q], v[q], sq);
            }
            wredsum2(sum, sq);
            float mean = sum * (1.f / 128.f);
            float var = sq * (1.f / 128.f) - mean * mean;
            float rstd = rsqrtf(var + EPS_LN);
#pragma unroll
            for (int q = 0; q < 4; q++) {
                float u = fmaf((v[q] - mean) * rstd, rg[q], rb[q]);
                hs[m][lane + 32 * q] = gelu_fast(u);
            }
        }
    }
    __syncthreads();

    {
        const int mg = t64 >> 5;
        const int o0 = (t & 31) * 2;
        float acc[8][2];
#pragma unroll
        for (int mm = 0; mm < 8; mm++) { acc[mm][0] = 0.f; acc[mm][1] = 0.f; }
#pragma unroll 2
        for (int j4 = 0; j4 < 32; j4++) {
            float2 wv[4];
#pragma unroll
            for (int j = 0; j < 4; j++)
                wv[j] = *reinterpret_cast<const float2*>(&w2[(j4 * 4 + j) * 64 + o0]);
#pragma unroll
            for (int mm = 0; mm < 8; mm++) {
                int m = mg * 8 + mm;
                float4 gv = *reinterpret_cast<const float4*>(&hs[m][j4 * 4]);
                acc[mm][0] = fmaf(gv.x, wv[0].x, acc[mm][0]);
                acc[mm][0] = fmaf(gv.y, wv[1].x, acc[mm][0]);
                acc[mm][0] = fmaf(gv.z, wv[2].x, acc[mm][0]);
                acc[mm][0] = fmaf(gv.w, wv[3].x, acc[mm][0]);
                acc[mm][1] = fmaf(gv.x, wv[0].y, acc[mm][1]);
                acc[mm][1] = fmaf(gv.y, wv[1].y, acc[mm][1]);
                acc[mm][1] = fmaf(gv.z, wv[2].y, acc[mm][1]);
                acc[mm][1] = fmaf(gv.w, wv[3].y, acc[mm][1]);
            }
        }
        float bo0 = b2[o0], bo1 = b2[o0 + 1];
#pragma unroll
        for (int mm = 0; mm < 8; mm++) {
            int n = n0 + mg * 8 + mm;
            if (n < N) {
                out[(size_t)n * 64 + o0] = acc[mm][0] + bo0;
                out[(size_t)n * 64 + o0 + 1] = acc[mm][1] + bo1;
            }
        }
    }
}

// ============================================================================
// ph role: H_ph[8x256] + b1 -> LN -> GELU -> Linear(128). Two 64-thr subgroups.
// ============================================================================
__device__ __forceinline__ void ph_role(int nb, char* smem_raw,
                                        const float* __restrict__ b1,
                                        const float* __restrict__ gm,
                                        const float* __restrict__ bt,
                                        const float* __restrict__ w2,
                                        const float* __restrict__ b2,
                                        float* __restrict__ out, int N) {
    const int t = threadIdx.x;
    const int g = t >> 6;
    const int t64 = t & 63;
    float (*hs)[256] = reinterpret_cast<float (*)[256]>(smem_raw + g * 8192);
    const int n0 = nb * 16 + g * 8;

    {
        int rem = N - n0;
        int lim = (rem > 8 ? 8 : (rem < 0 ? 0 : rem)) * 64;  // in float4 units
        const float4* src4 = reinterpret_cast<const float4*>(g_Hph + (size_t)n0 * 256);
        float4* hs4 = reinterpret_cast<float4*>(&hs[0][0]);
        float4 bv = reinterpret_cast<const float4*>(b1)[t64];
#pragma unroll
        for (int j = 0; j < 8; j++) {
            int idx = t64 + 64 * j;
            float4 v = make_float4(0.f, 0.f, 0.f, 0.f);
            if (idx < lim) v = __ldg(src4 + idx);
            v.x += bv.x; v.y += bv.y; v.z += bv.z; v.w += bv.w;
            hs4[idx] = v;
        }
    }
    __syncthreads();

    {
        const int w2i = t64 >> 5, lane = t & 31;
        float rg[8], rb[8];
#pragma unroll
        for (int q = 0; q < 8; q++) { rg[q] = gm[lane + 32 * q]; rb[q] = bt[lane + 32 * q]; }
        for (int mm = 0; mm < 4; mm++) {
            int m = w2i * 4 + mm;
            float v[8];
            float sum = 0.f, sq = 0.f;
#pragma unroll
            for (int q = 0; q < 8; q++) {
                v[q] = hs[m][lane + 32 * q];
                sum += v[q];
                sq = fmaf(v[q], v[q], sq);
            }
            wredsum2(sum, sq);
            float mean = sum * (1.f / 256.f);
            float var = sq * (1.f / 256.f) - mean * mean;
            float rstd = rsqrtf(var + EPS_LN);
#pragma unroll
            for (int q = 0; q < 8; q++) {
                float u = fmaf((v[q] - mean) * rstd, rg[q], rb[q]);
                hs[m][lane + 32 * q] = gelu_fast(u);
            }
        }
    }
    __syncthreads();

    {
        const int mg = t64 >> 5;
        const int o0 = (t & 31) * 4;
        float acc[4][4];
#pragma unroll
        for (int mm = 0; mm < 4; mm++)
#pragma unroll
            for (int oo = 0; oo < 4; oo++) acc[mm][oo] = 0.f;

#pragma unroll 2
        for (int j4 = 0; j4 < 64; j4++) {
            float4 wv[4];
#pragma unroll
            for (int j = 0; j < 4; j++)
                wv[j] = *reinterpret_cast<const float4*>(&w2[(j4 * 4 + j) * 128 + o0]);
#pragma unroll
            for (int mm = 0; mm < 4; mm++) {
                int m = mg * 4 + mm;
                float4 gv = *reinterpret_cast<const float4*>(&hs[m][j4 * 4]);
                float gvals[4] = {gv.x, gv.y, gv.z, gv.w};
#pragma unroll
                for (int j = 0; j < 4; j++) {
                    acc[mm][0] = fmaf(gvals[j], wv[j].x, acc[mm][0]);
                    acc[mm][1] = fmaf(gvals[j], wv[j].y, acc[mm][1]);
                    acc[mm][2] = fmaf(gvals[j], wv[j].z, acc[mm][2]);
                    acc[mm][3] = fmaf(gvals[j], wv[j].w, acc[mm][3]);
                }
            }
        }
        float4 bo = *reinterpret_cast<const float4*>(&b2[o0]);
#pragma unroll
        for (int mm = 0; mm < 4; mm++) {
            int n = n0 + mg * 4 + mm;
            if (n < N) {
                float4 rr;
                rr.x = acc[mm][0] + bo.x;
                rr.y = acc[mm][1] + bo.y;
                rr.z = acc[mm][2] + bo.z;
                rr.w = acc[mm][3] + bo.w;
                *reinterpret_cast<float4*>(&out[(size_t)n * 128 + o0]) = rr;
            }
        }
    }
}

// ============================================================================
// Mega kernel: role-interleaved edge + fr + ph (8:3 block pattern)
// ============================================================================
__global__ __launch_bounds__(128, 6) void k_mega(
    const int* __restrict__ ei, int N, int E,
    const float* __restrict__ fr_b1,
    const float* __restrict__ fr_g, const float* __restrict__ fr_be,
    const float* __restrict__ fr_w2, const float* __restrict__ fr_b2,
    const float* __restrict__ ph_b1,
    const float* __restrict__ ph_g, const float* __restrict__ ph_be,
    const float* __restrict__ ph_w2, const float* __restrict__ ph_b2,
    const float* __restrict__ sp_g, const float* __restrict__ sp_be,
    const float* __restrict__ sp_w2, const float* __restrict__ sp_b2,
    float* __restrict__ out_sp, float* __restrict__ out_fr, float* __restrict__ out_ph,
    int nfr, int nph) {
    __shared__ __align__(16) char smem_raw[16384];
    const int b = blockIdx.x;
    const int gid = b / 11;
    const int slot = b - gid * 11;

    if (slot < 8) {
        edge_role(gid * 8 + slot, ei, E, sp_g, sp_be, sp_w2, sp_b2, out_sp);
    } else {
        int nb = gid * 3 + (slot - 8);
        if (nb < nfr) {
            fr_role(nb, smem_raw, fr_b1, fr_g, fr_be, fr_w2, fr_b2, out_fr, N);
        } else if (nb < nfr + nph) {
            ph_role(nb - nfr, smem_raw, ph_b1, ph_g, ph_be, ph_w2, ph_b2, out_ph, N);
        }
    }
}

// ============================================================================
// launch
// ============================================================================
extern "C" void kernel_launch(void* const* d_in, const int* in_sizes, int n_in,
                              void* d_out, int out_size) {
    const float* x = (const float*)d_in[0];
    const int* ei = (const int*)d_in[1];
    const float* sp_w1 = (const float*)d_in[2];
    const float* sp_b1 = (const float*)d_in[3];
    const float* sp_g = (const float*)d_in[4];
    const float* sp_be = (const float*)d_in[5];
    const float* sp_w2 = (const float*)d_in[6];
    const float* sp_b2 = (const float*)d_in[7];
    const float* fr_w1 = (const float*)d_in[8];
    const float* fr_b1 = (const float*)d_in[9];
    const float* fr_g = (const float*)d_in[10];
    const float* fr_be = (const float*)d_in[11];
    const float* fr_w2 = (const float*)d_in[12];
    const float* fr_b2 = (const float*)d_in[13];
    const float* ph_w1 = (const float*)d_in[14];
    const float* ph_b1 = (const float*)d_in[15];
    const float* ph_g = (const float*)d_in[16];
    const float* ph_be = (const float*)d_in[17];
    const float* ph_w2 = (const float*)d_in[18];
    const float* ph_b2 = (const float*)d_in[19];

    const int N = in_sizes[0] / 64;
    const int E = in_sizes[1] / 2;

    float* out_sp = (float*)d_out;             // [E]
    float* out_fr = out_sp + (size_t)E;        // [N,64]
    float* out_ph = out_fr + (size_t)N * 64;   // [N,128]

    // Phase 0: weight transpose + bf16 split
    k_prep<<<(896 * 64 + 255) / 256, 256>>>(sp_w1, fr_w1, ph_w1);

    // Phase 1: fused HMMA GEMM1 -> P/Q, H_fr, H_ph
    k_gemm1<<<(N + 63) / 64, 128>>>(x, sp_b1, N);

    // Phase 2: role-interleaved mega kernel
    const int nfr = (N + 31) / 32;
    const int nph = (N + 15) / 16;
    const int node_blocks = nfr + nph;
    const long ewarps = ((long)E + EPW - 1) / EPW;
    const int eblk = (int)((ewarps + 3) / 4);
    int Ga = (node_blocks + 2) / 3;
    int Gb = (eblk + 7) / 8;
    int G = Ga > Gb ? Ga : Gb;

    k_mega<<<G * 11, 128>>>(ei, N, E,
                            fr_b1, fr_g, fr_be, fr_w2, fr_b2,
                            ph_b1, ph_g, ph_be, ph_w2, ph_b2,
                            sp_g, sp_be, sp_w2, sp_b2,
                            out_sp, out_fr, out_ph, nfr, nph);
}

// round 10
// speedup vs baseline: 1.2490x; 1.2490x over previous
#include <cuda_runtime.h>
#include <stdint.h>
#include <math.h>

#define NMAX 50000
#define EPS_LN 1e-5f
#define EPW 16

typedef unsigned long long u64;

// Scratch: P = x @ sp_w1[0:64,:] + sp_b1, Q = x @ sp_w1[64:128,:]   (each [N,256])
__device__ float g_P[(size_t)NMAX * 256];
__device__ float g_Q[(size_t)NMAX * 256];

// ---------------- f32x2 packed helpers ----------------
__device__ __forceinline__ u64 f2pack(float lo, float hi) {
    u64 r; asm("mov.b64 %0, {%1, %2};" : "=l"(r) : "f"(lo), "f"(hi)); return r;
}
__device__ __forceinline__ void f2unpack(u64 v, float& lo, float& hi) {
    asm("mov.b64 {%0, %1}, %2;" : "=f"(lo), "=f"(hi) : "l"(v));
}
__device__ __forceinline__ u64 dup2(float v) { return f2pack(v, v); }
__device__ __forceinline__ u64 fma2(u64 a, u64 b, u64 c) {
    u64 d; asm("fma.rn.f32x2 %0, %1, %2, %3;" : "=l"(d) : "l"(a), "l"(b), "l"(c)); return d;
}
__device__ __forceinline__ u64 add2(u64 a, u64 b) {
    u64 d; asm("add.rn.f32x2 %0, %1, %2;" : "=l"(d) : "l"(a), "l"(b)); return d;
}
__device__ __forceinline__ u64 mul2(u64 a, u64 b) {
    u64 d; asm("mul.rn.f32x2 %0, %1, %2;" : "=l"(d) : "l"(a), "l"(b)); return d;
}
__device__ __forceinline__ float rcp_fast(float x) {
    float r; asm("rcp.approx.f32 %0, %1;" : "=f"(r) : "f"(x)); return r;
}
__device__ __forceinline__ float ex2_fast(float x) {
    float r; asm("ex2.approx.f32 %0, %1;" : "=f"(r) : "f"(x)); return r;
}

__device__ __forceinline__ float wredsum(float v) {
#pragma unroll
    for (int o = 16; o > 0; o >>= 1) v += __shfl_xor_sync(0xffffffffu, v, o);
    return v;
}
__device__ __forceinline__ void wredsum2(float& a, float& b) {
#pragma unroll
    for (int o = 16; o > 0; o >>= 1) {
        float ta = __shfl_xor_sync(0xffffffffu, a, o);
        float tb = __shfl_xor_sync(0xffffffffu, b, o);
        a += ta;
        b += tb;
    }
}
// 4 interleaved butterfly chains — overlap SHFL latency across 4 reductions
__device__ __forceinline__ void wredsum4(float& a, float& b, float& c, float& d) {
#pragma unroll
    for (int o = 16; o > 0; o >>= 1) {
        float ta = __shfl_xor_sync(0xffffffffu, a, o);
        float tb = __shfl_xor_sync(0xffffffffu, b, o);
        float tc = __shfl_xor_sync(0xffffffffu, c, o);
        float td = __shfl_xor_sync(0xffffffffu, d, o);
        a += ta; b += tb; c += tc; d += td;
    }
}

// fast GELU via Hastings 3-term erf (A&S 7.1.25, |err| <= 2.5e-5)
__device__ __forceinline__ float gelu_fast(float u) {
    float z = 0.70710678118654752f * u;
    float az = fabsf(z);
    float t = rcp_fast(fmaf(0.47047f, az, 1.0f));
    float poly = t * fmaf(t, fmaf(t, 0.7478556f, -0.0958798f), 0.3480242f);
    float e = ex2_fast(-az * az * 1.4426950408889634f);
    float erf_z = copysignf(fmaf(-poly, e, 1.0f), z);
    return 0.5f * u * (1.0f + erf_z);
}

// ============================================================================
// K1 v2: P,Q = x @ W_top (+b1), x @ W_bot.
// 32-node tile, 256 threads; thread owns ONE column of both P and Q.
// Halves per-block weight reload vs 16-node tile.
// ============================================================================
__global__ __launch_bounds__(256) void k_pq(const float* __restrict__ x,
                                            const float* __restrict__ w,   // [128,256]
                                            const float* __restrict__ b1,  // [256]
                                            int N) {
    __shared__ float xs[32][64];
    const int t = threadIdx.x;
    const int n0 = blockIdx.x * 32;

    {
        float4* xs4 = reinterpret_cast<float4*>(&xs[0][0]);
        const float4* x4 = reinterpret_cast<const float4*>(x);
#pragma unroll
        for (int i = t; i < 512; i += 256) {
            int node = n0 + (i >> 4);
            float4 v = make_float4(0.f, 0.f, 0.f, 0.f);
            if (node < N) v = x4[(size_t)node * 16 + (i & 15)];
            xs4[i] = v;
        }
    }
    __syncthreads();

    float aP[32], aQ[32];
#pragma unroll
    for (int m = 0; m < 32; m++) { aP[m] = 0.f; aQ[m] = 0.f; }

    const int c = t;
#pragma unroll 2
    for (int k4 = 0; k4 < 16; k4++) {
        float wp[4], wq[4];
#pragma unroll
        for (int j = 0; j < 4; j++) {
            int k = k4 * 4 + j;
            wp[j] = w[k * 256 + c];
            wq[j] = w[(64 + k) * 256 + c];
        }
#pragma unroll
        for (int m = 0; m < 32; m++) {
            float4 xv = *reinterpret_cast<const float4*>(&xs[m][k4 * 4]);
            float xa[4] = {xv.x, xv.y, xv.z, xv.w};
#pragma unroll
            for (int j = 0; j < 4; j++) {
                aP[m] = fmaf(xa[j], wp[j], aP[m]);
                aQ[m] = fmaf(xa[j], wq[j], aQ[m]);
            }
        }
    }

    const float bb = b1[c];
#pragma unroll
    for (int m = 0; m < 32; m++) {
        int n = n0 + m;
        if (n >= N) break;
        g_P[(size_t)n * 256 + c] = aP[m] + bb;
        g_Q[(size_t)n * 256 + c] = aQ[m];
    }
}

// ============================================================================
// Edge role: out = GELU(LN(P[row]+Q[col])) . w2 + b2
// DUAL-EDGE: 2 edges per iteration, 4-chain interleaved reductions (wredsum4),
// paired final reduction (wredsum2). f32x2 math throughout.
// ============================================================================
__device__ __forceinline__ void edge_role(int eb, const int* __restrict__ ei, int E,
                                          const float* __restrict__ gm,
                                          const float* __restrict__ bt,
                                          const float* __restrict__ w2,
                                          const float* __restrict__ b2p,
                                          float* __restrict__ out) {
    const int t = threadIdx.x;
    const int lane = t & 31;
    const int wid = t >> 5;

    long e0 = ((long)eb * 4 + wid) * EPW;
    if (e0 >= E) return;
    const int nE = (int)(E - e0 < EPW ? E - e0 : EPW);

    const float4* gmv = reinterpret_cast<const float4*>(gm);
    const float4* btv = reinterpret_cast<const float4*>(bt);
    const float4* w2v = reinterpret_cast<const float4*>(w2);
    float4 rga = gmv[lane], rgb = gmv[32 + lane];
    float4 rba = btv[lane], rbb = btv[32 + lane];
    float4 rwa = w2v[lane], rwb = w2v[32 + lane];

    const float RS2 = 0.70710678118654752f;
    u64 g2[4] = {f2pack(rga.x * RS2, rga.y * RS2), f2pack(rga.z * RS2, rga.w * RS2),
                 f2pack(rgb.x * RS2, rgb.y * RS2), f2pack(rgb.z * RS2, rgb.w * RS2)};
    u64 be2[4] = {f2pack(rba.x * RS2, rba.y * RS2), f2pack(rba.z * RS2, rba.w * RS2),
                  f2pack(rbb.x * RS2, rbb.y * RS2), f2pack(rbb.z * RS2, rbb.w * RS2)};
    u64 hw2[4] = {f2pack(rwa.x * RS2, rwa.y * RS2), f2pack(rwa.z * RS2, rwa.w * RS2),
                  f2pack(rwb.x * RS2, rwb.y * RS2), f2pack(rwb.z * RS2, rwb.w * RS2)};

    const u64 ONE2 = dup2(1.0f);
    const u64 PC = dup2(0.47047f);
    const u64 C3 = dup2(-0.7478556f);
    const u64 C2C = dup2(0.0958798f);
    const u64 C1 = dup2(-0.3480242f);
    const u64 NL2E = dup2(-1.4426950408889634f);
    const u64 AMASK = 0x7FFFFFFF7FFFFFFFull;
    const u64 SMASK = 0x8000000080000000ull;

    const float b2 = __ldg(b2p);

    const ulonglong2* P2v = reinterpret_cast<const ulonglong2*>(g_P);
    const ulonglong2* Q2v = reinterpret_cast<const ulonglong2*>(g_Q);

    // vectorized index load: lanes 0-15 row idx, lanes 16-31 col idx
    const int li = lane & 15;
    int idx = 0;
    if (li < nE) idx = ei[(lane < 16 ? e0 + li : (long)E + e0 + li)];

    for (int i = 0; i < nE; i += 2) {
        const int i2 = (i + 1 < nE) ? i + 1 : i;
        int rA = __shfl_sync(0xffffffffu, idx, i);
        int cA = __shfl_sync(0xffffffffu, idx, 16 + i);
        int rB = __shfl_sync(0xffffffffu, idx, i2);
        int cB = __shfl_sync(0xffffffffu, idx, 16 + i2);

        // 8 gathers issued together (MLP 8)
        ulonglong2 paA = P2v[(size_t)rA * 64 + lane];
        ulonglong2 pbA = P2v[(size_t)rA * 64 + 32 + lane];
        ulonglong2 qaA = Q2v[(size_t)cA * 64 + lane];
        ulonglong2 qbA = Q2v[(size_t)cA * 64 + 32 + lane];
        ulonglong2 paB = P2v[(size_t)rB * 64 + lane];
        ulonglong2 pbB = P2v[(size_t)rB * 64 + 32 + lane];
        ulonglong2 qaB = Q2v[(size_t)cB * 64 + lane];
        ulonglong2 qbB = Q2v[(size_t)cB * 64 + 32 + lane];

        u64 sA[4], sB[4];
        sA[0] = add2(paA.x, qaA.x);
        sA[1] = add2(paA.y, qaA.y);
        sA[2] = add2(pbA.x, qbA.x);
        sA[3] = add2(pbA.y, qbA.y);
        sB[0] = add2(paB.x, qaB.x);
        sB[1] = add2(paB.y, qaB.y);
        sB[2] = add2(pbB.x, qbB.x);
        sB[3] = add2(pbB.y, qbB.y);

        u64 sumA2 = add2(add2(sA[0], sA[1]), add2(sA[2], sA[3]));
        u64 sqA2 = fma2(sA[0], sA[0], fma2(sA[1], sA[1], fma2(sA[2], sA[2], mul2(sA[3], sA[3]))));
        u64 sumB2 = add2(add2(sB[0], sB[1]), add2(sB[2], sB[3]));
        u64 sqB2 = fma2(sB[0], sB[0], fma2(sB[1], sB[1], fma2(sB[2], sB[2], mul2(sB[3], sB[3]))));

        float xl, xh;
        f2unpack(sumA2, xl, xh);
        float sumA = xl + xh;
        f2unpack(sqA2, xl, xh);
        float sqA = xl + xh;
        f2unpack(sumB2, xl, xh);
        float sumB = xl + xh;
        f2unpack(sqB2, xl, xh);
        float sqB = xl + xh;

        wredsum4(sumA, sqA, sumB, sqB);

        float meanA = sumA * (1.f / 256.f);
        float varA = sqA * (1.f / 256.f) - meanA * meanA;
        float rstdA = rsqrtf(varA + EPS_LN);
        float meanB = sumB * (1.f / 256.f);
        float varB = sqB * (1.f / 256.f) - meanB * meanB;
        float rstdB = rsqrtf(varB + EPS_LN);

        u64 A2a = dup2(rstdA), Cca = dup2(-meanA * rstdA);
        u64 A2b = dup2(rstdB), Ccb = dup2(-meanB * rstdB);

        u64 accA = 0, accB = 0;
#pragma unroll
        for (int p = 0; p < 4; p++) {
            u64 uA = fma2(sA[p], A2a, Cca);
            u64 uB = fma2(sB[p], A2b, Ccb);
            u64 zA = fma2(uA, g2[p], be2[p]);
            u64 zB = fma2(uB, g2[p], be2[p]);
            u64 azA = zA & AMASK;
            u64 azB = zB & AMASK;
            u64 dA = fma2(azA, PC, ONE2);
            u64 dB = fma2(azB, PC, ONE2);
            float dAl, dAh, dBl, dBh;
            f2unpack(dA, dAl, dAh);
            f2unpack(dB, dBl, dBh);
            u64 tA = f2pack(rcp_fast(dAl), rcp_fast(dAh));
            u64 tB = f2pack(rcp_fast(dBl), rcp_fast(dBh));
            u64 pA = fma2(tA, C3, C2C);
            u64 pB = fma2(tB, C3, C2C);
            pA = fma2(tA, pA, C1);
            pB = fma2(tB, pB, C1);
            pA = mul2(pA, tA);
            pB = mul2(pB, tB);
            u64 zzA = mul2(azA, azA);
            u64 zzB = mul2(azB, azB);
            u64 mA = mul2(zzA, NL2E);
            u64 mB = mul2(zzB, NL2E);
            float mAl, mAh, mBl, mBh;
            f2unpack(mA, mAl, mAh);
            f2unpack(mB, mBl, mBh);
            u64 eA = f2pack(ex2_fast(mAl), ex2_fast(mAh));
            u64 eB = f2pack(ex2_fast(mBl), ex2_fast(mBh));
            u64 erfA = fma2(pA, eA, ONE2) | (zA & SMASK);
            u64 erfB = fma2(pB, eB, ONE2) | (zB & SMASK);
            accA = fma2(mul2(zA, add2(erfA, ONE2)), hw2[p], accA);
            accB = fma2(mul2(zB, add2(erfB, ONE2)), hw2[p], accB);
        }
        float aAl, aAh, aBl, aBh;
        f2unpack(accA, aAl, aAh);
        f2unpack(accB, aBl, aBh);
        float fA = aAl + aAh, fB = aBl + aBh;
        wredsum2(fA, fB);
        if (lane == 0) {
            out[e0 + i] = fA + b2;
            if (i + 1 < nE) out[e0 + i + 1] = fB + b2;
        }
    }
}

// ============================================================================
// fr role: x[64] -> Linear(128) -> LN -> GELU -> Linear(64)
// Two 64-thread subgroups, 16 nodes each (32 nodes/block). Scalar FMA.
// ============================================================================
__device__ __forceinline__ void fr_role(int nb, char* smem_raw,
                                        const float* __restrict__ x,
                                        const float* __restrict__ w1,
                                        const float* __restrict__ b1,
                                        const float* __restrict__ gm,
                                        const float* __restrict__ bt,
                                        const float* __restrict__ w2,
                                        const float* __restrict__ b2,
                                        float* __restrict__ out, int N) {
    const int t = threadIdx.x;
    const int g = t >> 6;
    const int t64 = t & 63;
    float (*xs)[64] = reinterpret_cast<float (*)[64]>(smem_raw + g * 4096);
    float (*hs)[128] = reinterpret_cast<float (*)[128]>(smem_raw + 8192 + g * 8192);
    const int n0 = nb * 32 + g * 16;

    {
        float4* xs4 = reinterpret_cast<float4*>(&xs[0][0]);
        const float4* x4 = reinterpret_cast<const float4*>(x);
#pragma unroll
        for (int i = t64; i < 256; i += 64) {
            int node = n0 + (i >> 4);
            float4 v = make_float4(0.f, 0.f, 0.f, 0.f);
            if (node < N) v = x4[(size_t)node * 16 + (i & 15)];
            xs4[i] = v;
        }
    }
    __syncthreads();

    {
        float a0[16], a1[16];
#pragma unroll
        for (int m = 0; m < 16; m++) { a0[m] = 0.f; a1[m] = 0.f; }
        const int c0 = t64, c1 = t64 + 64;
#pragma unroll 2
        for (int k4 = 0; k4 < 16; k4++) {
            float wr0[4], wr1[4];
#pragma unroll
            for (int j = 0; j < 4; j++) {
                int k = k4 * 4 + j;
                wr0[j] = w1[k * 128 + c0];
                wr1[j] = w1[k * 128 + c1];
            }
#pragma unroll
            for (int m = 0; m < 16; m++) {
                float4 xv = *reinterpret_cast<const float4*>(&xs[m][k4 * 4]);
                float xa[4] = {xv.x, xv.y, xv.z, xv.w};
#pragma unroll
                for (int j = 0; j < 4; j++) {
                    a0[m] = fmaf(xa[j], wr0[j], a0[m]);
                    a1[m] = fmaf(xa[j], wr1[j], a1[m]);
                }
            }
        }
        float bb0 = b1[c0], bb1 = b1[c1];
#pragma unroll
        for (int m = 0; m < 16; m++) { hs[m][c0] = a0[m] + bb0; hs[m][c1] = a1[m] + bb1; }
    }
    __syncthreads();

    {
        const int w2i = t64 >> 5, lane = t & 31;
        float rg[4], rb[4];
#pragma unroll
        for (int q = 0; q < 4; q++) { rg[q] = gm[lane + 32 * q]; rb[q] = bt[lane + 32 * q]; }
        for (int mm = 0; mm < 8; mm++) {
            int m = w2i * 8 + mm;
            float v[4];
            float sum = 0.f, sq = 0.f;
#pragma unroll
            for (int q = 0; q < 4; q++) {
                v[q] = hs[m][lane + 32 * q];
                sum += v[q];
                sq = fmaf(v[q], v[q], sq);
            }
            wredsum2(sum, sq);
            float mean = sum * (1.f / 128.f);
            float var = sq * (1.f / 128.f) - mean * mean;
            float rstd = rsqrtf(var + EPS_LN);
#pragma unroll
            for (int q = 0; q < 4; q++) {
                float u = fmaf((v[q] - mean) * rstd, rg[q], rb[q]);
                hs[m][lane + 32 * q] = gelu_fast(u);
            }
        }
    }
    __syncthreads();

    {
        const int mg = t64 >> 5;
        const int o0 = (t & 31) * 2;
        float acc[8][2];
#pragma unroll
        for (int mm = 0; mm < 8; mm++) { acc[mm][0] = 0.f; acc[mm][1] = 0.f; }
#pragma unroll 2
        for (int j4 = 0; j4 < 32; j4++) {
            float2 wv[4];
#pragma unroll
            for (int j = 0; j < 4; j++)
                wv[j] = *reinterpret_cast<const float2*>(&w2[(j4 * 4 + j) * 64 + o0]);
#pragma unroll
            for (int mm = 0; mm < 8; mm++) {
                int m = mg * 8 + mm;
                float4 gv = *reinterpret_cast<const float4*>(&hs[m][j4 * 4]);
                acc[mm][0] = fmaf(gv.x, wv[0].x, acc[mm][0]);
                acc[mm][0] = fmaf(gv.y, wv[1].x, acc[mm][0]);
                acc[mm][0] = fmaf(gv.z, wv[2].x, acc[mm][0]);
                acc[mm][0] = fmaf(gv.w, wv[3].x, acc[mm][0]);
                acc[mm][1] = fmaf(gv.x, wv[0].y, acc[mm][1]);
                acc[mm][1] = fmaf(gv.y, wv[1].y, acc[mm][1]);
                acc[mm][1] = fmaf(gv.z, wv[2].y, acc[mm][1]);
                acc[mm][1] = fmaf(gv.w, wv[3].y, acc[mm][1]);
            }
        }
        float bo0 = b2[o0], bo1 = b2[o0 + 1];
#pragma unroll
        for (int mm = 0; mm < 8; mm++) {
            int n = n0 + mg * 8 + mm;
            if (n < N) {
                out[(size_t)n * 64 + o0] = acc[mm][0] + bo0;
                out[(size_t)n * 64 + o0 + 1] = acc[mm][1] + bo1;
            }
        }
    }
}

// ============================================================================
// ph role: x[64] -> Linear(256) -> LN -> GELU -> Linear(128)
// Two 64-thread subgroups, 8 nodes each (16 nodes/block). Scalar FMA.
// ============================================================================
__device__ __forceinline__ void ph_role(int nb, char* smem_raw,
                                        const float* __restrict__ x,
                                        const float* __restrict__ w1,
                                        const float* __restrict__ b1,
                                        const float* __restrict__ gm,
                                        const float* __restrict__ bt,
                                        const float* __restrict__ w2,
                                        const float* __restrict__ b2,
                                        float* __restrict__ out, int N) {
    const int t = threadIdx.x;
    const int g = t >> 6;
    const int t64 = t & 63;
    float (*xs)[64] = reinterpret_cast<float (*)[64]>(smem_raw + g * 2048);
    float (*hs)[256] = reinterpret_cast<float (*)[256]>(smem_raw + 4096 + g * 8192);
    const int n0 = nb * 16 + g * 8;

    {
        float4* xs4 = reinterpret_cast<float4*>(&xs[0][0]);
        const float4* x4 = reinterpret_cast<const float4*>(x);
#pragma unroll
        for (int i = t64; i < 128; i += 64) {
            int node = n0 + (i >> 4);
            float4 v = make_float4(0.f, 0.f, 0.f, 0.f);
            if (node < N) v = x4[(size_t)node * 16 + (i & 15)];
            xs4[i] = v;
        }
    }
    __syncthreads();

    {
        float a[4][8];
#pragma unroll
        for (int cc = 0; cc < 4; cc++)
#pragma unroll
            for (int m = 0; m < 8; m++) a[cc][m] = 0.f;

#pragma unroll 2
        for (int k4 = 0; k4 < 16; k4++) {
            float wr[4][4];
#pragma unroll
            for (int cc = 0; cc < 4; cc++)
#pragma unroll
                for (int j = 0; j < 4; j++)
                    wr[cc][j] = w1[(k4 * 4 + j) * 256 + t64 + 64 * cc];
#pragma unroll
            for (int m = 0; m < 8; m++) {
                float4 xv = *reinterpret_cast<const float4*>(&xs[m][k4 * 4]);
                float xa[4] = {xv.x, xv.y, xv.z, xv.w};
#pragma unroll
                for (int cc = 0; cc < 4; cc++)
#pragma unroll
                    for (int j = 0; j < 4; j++)
                        a[cc][m] = fmaf(xa[j], wr[cc][j], a[cc][m]);
            }
        }
#pragma unroll
        for (int cc = 0; cc < 4; cc++) {
            float bb = b1[t64 + 64 * cc];
#pragma unroll
            for (int m = 0; m < 8; m++) hs[m][t64 + 64 * cc] = a[cc][m] + bb;
        }
    }
    __syncthreads();

    {
        const int w2i = t64 >> 5, lane = t & 31;
        float rg[8], rb[8];
#pragma unroll
        for (int q = 0; q < 8; q++) { rg[q] = gm[lane + 32 * q]; rb[q] = bt[lane + 32 * q]; }
        for (int mm = 0; mm < 4; mm++) {
            int m = w2i * 4 + mm;
            float v[8];
            float sum = 0.f, sq = 0.f;
#pragma unroll
            for (int q = 0; q < 8; q++) {
                v[q] = hs[m][lane + 32 * q];
                sum += v[q];
                sq = fmaf(v[q], v[q], sq);
            }
            wredsum2(sum, sq);
            float mean = sum * (1.f / 256.f);
            float var = sq * (1.f / 256.f) - mean * mean;
            float rstd = rsqrtf(var + EPS_LN);
#pragma unroll
            for (int q = 0; q < 8; q++) {
                float u = fmaf((v[q] - mean) * rstd, rg[q], rb[q]);
                hs[m][lane + 32 * q] = gelu_fast(u);
            }
        }
    }
    __syncthreads();

    {
        const int mg = t64 >> 5;
        const int o0 = (t & 31) * 4;
        float acc[4][4];
#pragma unroll
        for (int mm = 0; mm < 4; mm++)
#pragma unroll
            for (int oo = 0; oo < 4; oo++) acc[mm][oo] = 0.f;

#pragma unroll 2
        for (int j4 = 0; j4 < 64; j4++) {
            float4 wv[4];
#pragma unroll
            for (int j = 0; j < 4; j++)
                wv[j] = *reinterpret_cast<const float4*>(&w2[(j4 * 4 + j) * 128 + o0]);
#pragma unroll
            for (int mm = 0; mm < 4; mm++) {
                int m = mg * 4 + mm;
                float4 gv = *reinterpret_cast<const float4*>(&hs[m][j4 * 4]);
                float gvals[4] = {gv.x, gv.y, gv.z, gv.w};
#pragma unroll
                for (int j = 0; j < 4; j++) {
                    acc[mm][0] = fmaf(gvals[j], wv[j].x, acc[mm][0]);
                    acc[mm][1] = fmaf(gvals[j], wv[j].y, acc[mm][1]);
                    acc[mm][2] = fmaf(gvals[j], wv[j].z, acc[mm][2]);
                    acc[mm][3] = fmaf(gvals[j], wv[j].w, acc[mm][3]);
                }
            }
        }
        float4 bo = *reinterpret_cast<const float4*>(&b2[o0]);
#pragma unroll
        for (int mm = 0; mm < 4; mm++) {
            int n = n0 + mg * 4 + mm;
            if (n < N) {
                float4 rr;
                rr.x = acc[mm][0] + bo.x;
                rr.y = acc[mm][1] + bo.y;
                rr.z = acc[mm][2] + bo.z;
                rr.w = acc[mm][3] + bo.w;
                *reinterpret_cast<float4*>(&out[(size_t)n * 128 + o0]) = rr;
            }
        }
    }
}

// ============================================================================
// Mega kernel: role-interleaved edge + fr + ph (8:3 block pattern)
// ============================================================================
__global__ __launch_bounds__(128, 6) void k_mega(
    const float* __restrict__ x, const int* __restrict__ ei, int N, int E,
    const float* __restrict__ fr_w1, const float* __restrict__ fr_b1,
    const float* __restrict__ fr_g, const float* __restrict__ fr_be,
    const float* __restrict__ fr_w2, const float* __restrict__ fr_b2,
    const float* __restrict__ ph_w1, const float* __restrict__ ph_b1,
    const float* __restrict__ ph_g, const float* __restrict__ ph_be,
    const float* __restrict__ ph_w2, const float* __restrict__ ph_b2,
    const float* __restrict__ sp_g, const float* __restrict__ sp_be,
    const float* __restrict__ sp_w2, const float* __restrict__ sp_b2,
    float* __restrict__ out_sp, float* __restrict__ out_fr, float* __restrict__ out_ph,
    int nfr, int nph) {
    __shared__ __align__(16) char smem_raw[24576];
    const int b = blockIdx.x;
    const int gid = b / 11;
    const int slot = b - gid * 11;

    if (slot < 8) {
        edge_role(gid * 8 + slot, ei, E, sp_g, sp_be, sp_w2, sp_b2, out_sp);
    } else {
        int nb = gid * 3 + (slot - 8);
        if (nb < nfr) {
            fr_role(nb, smem_raw, x, fr_w1, fr_b1, fr_g, fr_be, fr_w2, fr_b2, out_fr, N);
        } else if (nb < nfr + nph) {
            ph_role(nb - nfr, smem_raw, x, ph_w1, ph_b1, ph_g, ph_be, ph_w2, ph_b2, out_ph, N);
        }
    }
}

// ============================================================================
// launch
// ============================================================================
extern "C" void kernel_launch(void* const* d_in, const int* in_sizes, int n_in,
                              void* d_out, int out_size) {
    const float* x = (const float*)d_in[0];
    const int* ei = (const int*)d_in[1];
    const float* sp_w1 = (const float*)d_in[2];
    const float* sp_b1 = (const float*)d_in[3];
    const float* sp_g = (const float*)d_in[4];
    const float* sp_be = (const float*)d_in[5];
    const float* sp_w2 = (const float*)d_in[6];
    const float* sp_b2 = (const float*)d_in[7];
    const float* fr_w1 = (const float*)d_in[8];
    const float* fr_b1 = (const float*)d_in[9];
    const float* fr_g = (const float*)d_in[10];
    const float* fr_be = (const float*)d_in[11];
    const float* fr_w2 = (const float*)d_in[12];
    const float* fr_b2 = (const float*)d_in[13];
    const float* ph_w1 = (const float*)d_in[14];
    const float* ph_b1 = (const float*)d_in[15];
    const float* ph_g = (const float*)d_in[16];
    const float* ph_be = (const float*)d_in[17];
    const float* ph_w2 = (const float*)d_in[18];
    const float* ph_b2 = (const float*)d_in[19];

    const int N = in_sizes[0] / 64;
    const int E = in_sizes[1] / 2;

    float* out_sp = (float*)d_out;             // [E]
    float* out_fr = out_sp + (size_t)E;        // [N,64]
    float* out_ph = out_fr + (size_t)N * 64;   // [N,128]

    // Phase 1: P/Q precompute (edge branch depends on it)
    k_pq<<<(N + 31) / 32, 256>>>(x, sp_w1, sp_b1, N);

    // Phase 2: role-interleaved mega kernel
    const int nfr = (N + 31) / 32;
    const int nph = (N + 15) / 16;
    const int node_blocks = nfr + nph;
    const long ewarps = ((long)E + EPW - 1) / EPW;
    const int eblk = (int)((ewarps + 3) / 4);
    int Ga = (node_blocks + 2) / 3;
    int Gb = (eblk + 7) / 8;
    int G = Ga > Gb ? Ga : Gb;

    k_mega<<<G * 11, 128>>>(x, ei, N, E,
                            fr_w1, fr_b1, fr_g, fr_be, fr_w2, fr_b2,
                            ph_w1, ph_b1, ph_g, ph_be, ph_w2, ph_b2,
                            sp_g, sp_be, sp_w2, sp_b2,
                            out_sp, out_fr, out_ph, nfr, nph);
}